// round 1
// baseline (speedup 1.0000x reference)
#include <cuda_runtime.h>

// FeaturesLoss: contrastive loss over B=8192, D=128 features, scalar output.
// Strategy: upper-triangular 128x128 tiling of the gram matrix, fused epilogue,
// deterministic two-stage reduction.

#define BN    8192
#define DIM   128
#define TILE  128
#define NT    (BN / TILE)          // 64 tile rows
#define NBLK  (NT * (NT + 1) / 2)  // 2080 upper-tri tile blocks
#define SSTR  130                  // smem row stride (floats), breaks bank conflicts
#define MARGIN 2.0f

__device__ float      g_sq[BN];
__device__ int        g_lab[BN];
__device__ float      g_partials[NBLK];
__device__ long long  g_poscnt[NBLK];

// ---------------------------------------------------------------------------
// Kernel 0: per-row squared norms + label int conversion (with int64/int32
// runtime dtype detection; probing only bytes valid under both layouts).
// ---------------------------------------------------------------------------
__global__ void prep_kernel(const float* __restrict__ F,
                            const void* __restrict__ labels_raw) {
    int warp = (blockIdx.x * blockDim.x + threadIdx.x) >> 5;
    int lane = threadIdx.x & 31;
    if (warp >= BN) return;

    // dtype probe: if int64, high words of first 32 labels are all zero.
    const int* w = (const int*)labels_raw;
    int probe = w[2 * lane + 1];
    unsigned is64 = __all_sync(0xffffffffu, probe == 0);

    const float4* row = (const float4*)(F + (size_t)warp * DIM);
    float4 f = row[lane];                 // 32 lanes * 4 = 128 floats
    float s = f.x * f.x + f.y * f.y + f.z * f.z + f.w * f.w;
    #pragma unroll
    for (int off = 16; off; off >>= 1)
        s += __shfl_xor_sync(0xffffffffu, s, off);

    if (lane == 0) {
        g_sq[warp] = s;
        int lab;
        if (is64) lab = (int)((const long long*)labels_raw)[warp];
        else      lab = w[warp];
        g_lab[warp] = lab;
    }
}

// ---------------------------------------------------------------------------
// Kernel 1: one 128x128 tile of pairs per block (upper triangle only).
// K-major smem tiles, 8x8 register microtiles, fused loss epilogue.
// ---------------------------------------------------------------------------
__global__ void __launch_bounds__(256, 1)
tile_kernel(const float* __restrict__ F) {
    extern __shared__ float smem[];
    float* As = smem;                 // [DIM][SSTR] K-major: As[k*SSTR + r]
    float* Bs = smem + DIM * SSTR;

    // map linear block id -> (bi, bj), bi <= bj
    int idx = blockIdx.x;
    int bi = 0;
    while (idx >= NT - bi) { idx -= NT - bi; bi++; }
    int bj = bi + idx;
    bool diag = (bi == bj);

    int i0 = bi * TILE, j0 = bj * TILE;
    int t = threadIdx.x;

    // load tiles (transpose to K-major); skip B load on diagonal blocks
    const float4* F4 = (const float4*)F;
    for (int v = t; v < TILE * 32; v += 256) {
        int r  = v >> 5;        // row within tile 0..127
        int c4 = v & 31;        // float4 column 0..31
        float4 fa = F4[(size_t)(i0 + r) * 32 + c4];
        As[(4 * c4 + 0) * SSTR + r] = fa.x;
        As[(4 * c4 + 1) * SSTR + r] = fa.y;
        As[(4 * c4 + 2) * SSTR + r] = fa.z;
        As[(4 * c4 + 3) * SSTR + r] = fa.w;
        if (!diag) {
            float4 fb = F4[(size_t)(j0 + r) * 32 + c4];
            Bs[(4 * c4 + 0) * SSTR + r] = fb.x;
            Bs[(4 * c4 + 1) * SSTR + r] = fb.y;
            Bs[(4 * c4 + 2) * SSTR + r] = fb.z;
            Bs[(4 * c4 + 3) * SSTR + r] = fb.w;
        }
    }
    __syncthreads();

    const float* Bp = diag ? As : Bs;

    int tx = t & 15, ty = t >> 4;

    float acc[8][8];
    #pragma unroll
    for (int u = 0; u < 8; u++)
        #pragma unroll
        for (int v = 0; v < 8; v++) acc[u][v] = 0.0f;

    #pragma unroll 4
    for (int k = 0; k < DIM; k++) {
        float a[8], b[8];
        #pragma unroll
        for (int u = 0; u < 8; u++) a[u] = As[k * SSTR + ty * 8 + u];
        #pragma unroll
        for (int v = 0; v < 8; v++) b[v] = Bp[k * SSTR + tx * 8 + v];
        #pragma unroll
        for (int u = 0; u < 8; u++)
            #pragma unroll
            for (int v = 0; v < 8; v++)
                acc[u][v] = fmaf(a[u], b[v], acc[u][v]);
    }

    // ---- fused epilogue ----
    float sqi[8], sqj[8];
    int   li[8],  lj[8];
    #pragma unroll
    for (int u = 0; u < 8; u++) {
        int gi = i0 + ty * 8 + u;
        sqi[u] = g_sq[gi];  li[u] = g_lab[gi];
    }
    #pragma unroll
    for (int v = 0; v < 8; v++) {
        int gj = j0 + tx * 8 + v;
        sqj[v] = g_sq[gj];  lj[v] = g_lab[gj];
    }

    float lsum = 0.0f;
    int   lcnt = 0;
    #pragma unroll
    for (int u = 0; u < 8; u++) {
        int gi = i0 + ty * 8 + u;
        #pragma unroll
        for (int v = 0; v < 8; v++) {
            int gj = j0 + tx * 8 + v;
            if (diag && gi == gj) continue;
            float d2 = fmaxf(sqi[u] + sqj[v] - 2.0f * acc[u][v], 0.0f);
            if (li[u] == lj[v]) {
                lsum += d2;
                lcnt++;
            } else if (d2 < MARGIN * MARGIN) {   // sqrt essentially never taken
                float h = MARGIN - sqrtf(d2);
                lsum += h * h;
            }
        }
    }

    // ---- deterministic block reduction ----
    int lane = t & 31, wid = t >> 5;
    #pragma unroll
    for (int off = 16; off; off >>= 1) {
        lsum += __shfl_xor_sync(0xffffffffu, lsum, off);
        lcnt += __shfl_xor_sync(0xffffffffu, lcnt, off);
    }
    __shared__ float rbuf[8];
    __shared__ int   rcnt[8];
    if (lane == 0) { rbuf[wid] = lsum; rcnt[wid] = lcnt; }
    __syncthreads();
    if (t == 0) {
        float s = 0.0f; long long c = 0;
        #pragma unroll
        for (int wd = 0; wd < 8; wd++) { s += rbuf[wd]; c += rcnt[wd]; }
        float fac = diag ? 1.0f : 2.0f;
        g_partials[blockIdx.x] = s * fac;
        g_poscnt[blockIdx.x]   = c * (diag ? 1LL : 2LL);
    }
}

// ---------------------------------------------------------------------------
// Kernel 2: fixed-order finalize reduction -> scalar loss.
// ---------------------------------------------------------------------------
__global__ void finalize_kernel(float* __restrict__ out) {
    int t = threadIdx.x;
    double s = 0.0; long long c = 0;
    for (int i = t; i < NBLK; i += 256) {
        s += (double)g_partials[i];
        c += g_poscnt[i];
    }
    __shared__ double    sd[256];
    __shared__ long long sc[256];
    sd[t] = s; sc[t] = c;
    __syncthreads();
    for (int off = 128; off; off >>= 1) {
        if (t < off) { sd[t] += sd[t + off]; sc[t] += sc[t + off]; }
        __syncthreads();
    }
    if (t == 0) {
        double total = sd[0];
        double denom = (double)((long long)BN * (BN - 1));
        out[0] = (float)(sc[0] > 0 ? total / denom : total);
    }
}

// ---------------------------------------------------------------------------
extern "C" void kernel_launch(void* const* d_in, const int* in_sizes, int n_in,
                              void* d_out, int out_size) {
    const float* F      = (const float*)d_in[0];
    const void*  labels = d_in[1];
    float*       out    = (float*)d_out;

    size_t smem_bytes = (size_t)2 * DIM * SSTR * sizeof(float);  // 133120 B
    cudaFuncSetAttribute(tile_kernel,
                         cudaFuncAttributeMaxDynamicSharedMemorySize,
                         (int)smem_bytes);

    prep_kernel<<<BN / 8, 256>>>(F, labels);
    tile_kernel<<<NBLK, 256, smem_bytes>>>(F);
    finalize_kernel<<<1, 256>>>(out);
}

// round 5
// speedup vs baseline: 1.8308x; 1.8308x over previous
#include <cuda_runtime.h>
#include <cstdint>

// FeaturesLoss via legacy tensor-core path: mma.sync.m16n8k8 tf32 (compiles on
// plain sm_103 target; tcgen05 requires the 'a' feature the harness PTX lacks).
// Upper-triangular 128x128 gram tiles, fused loss epilogue, deterministic sum.

#define BN    8192
#define DIM   128
#define TILE  128
#define NT    (BN / TILE)          // 64
#define NBLK  (NT * (NT + 1) / 2)  // 2080
#define MARGIN 2.0f
#define SSTR  132                  // smem row stride in floats (528 B, 16B-aligned)

__device__ float      g_sq[BN];
__device__ int        g_lab[BN];
__device__ float      g_partials[NBLK];
__device__ long long  g_poscnt[NBLK];

__device__ __forceinline__ uint32_t f2tf32(float x) {
    uint32_t r;
    asm("cvt.rna.tf32.f32 %0, %1;" : "=r"(r) : "f"(x));
    return r;
}

__device__ __forceinline__ void mma_tf32(float c[4], uint32_t a0, uint32_t a1,
                                         uint32_t a2, uint32_t a3,
                                         uint32_t b0, uint32_t b1) {
    asm volatile(
        "mma.sync.aligned.m16n8k8.row.col.f32.tf32.tf32.f32 "
        "{%0,%1,%2,%3}, {%4,%5,%6,%7}, {%8,%9}, {%0,%1,%2,%3};"
        : "+f"(c[0]), "+f"(c[1]), "+f"(c[2]), "+f"(c[3])
        : "r"(a0), "r"(a1), "r"(a2), "r"(a3), "r"(b0), "r"(b1));
}

// ---------------------------------------------------------------------------
// Kernel 0: per-row squared norms + label conversion (int64/int32 probe).
// ---------------------------------------------------------------------------
__global__ void prep_kernel(const float* __restrict__ F,
                            const void* __restrict__ labels_raw) {
    int warp = (blockIdx.x * blockDim.x + threadIdx.x) >> 5;
    int lane = threadIdx.x & 31;
    if (warp >= BN) return;

    const int* w = (const int*)labels_raw;
    int probe = w[2 * lane + 1];
    unsigned is64 = __all_sync(0xffffffffu, probe == 0);

    const float4* row = (const float4*)(F + (size_t)warp * DIM);
    float4 f = row[lane];
    float s = f.x * f.x + f.y * f.y + f.z * f.z + f.w * f.w;
    #pragma unroll
    for (int off = 16; off; off >>= 1)
        s += __shfl_xor_sync(0xffffffffu, s, off);

    if (lane == 0) {
        g_sq[warp] = s;
        int lab;
        if (is64) lab = (int)((const long long*)labels_raw)[warp];
        else      lab = w[warp];
        g_lab[warp] = lab;
    }
}

// ---------------------------------------------------------------------------
// Kernel 1: one 128x128 pair tile per CTA. 8 warps; warp (wm, wn) computes a
// 64x32 sub-tile as 4x4 m16n8k8 tf32 mma fragments over 16 K-steps.
// ---------------------------------------------------------------------------
__global__ void __launch_bounds__(256, 1)
tile_kernel(const float* __restrict__ F) {
    extern __shared__ float smem[];
    float* As  = smem;                       // [128][SSTR] tf32 bits, row i-major
    float* Bs  = smem + TILE * SSTR;         // [128][SSTR] tf32 bits, row j-major
    float* sqI = smem + 2 * TILE * SSTR;     // [128]
    float* sqJ = sqI + TILE;                 // [128]
    int*   lbI = (int*)(sqJ + TILE);         // [128]
    int*   lbJ = lbI + TILE;                 // [128]

    int t = threadIdx.x;
    int wid = t >> 5, lane = t & 31;
    int gid = lane >> 2, tig = lane & 3;     // groupID / threadID-in-group

    // map linear block id -> (bi, bj), bi <= bj
    int idx = blockIdx.x;
    int bi = 0;
    while (idx >= NT - bi) { idx -= NT - bi; bi++; }
    int bj = bi + idx;
    bool diag = (bi == bj);
    int i0 = bi * TILE, j0 = bj * TILE;

    // stage per-row sq/labels
    if (t < TILE) {
        sqI[t] = g_sq[i0 + t];  lbI[t] = g_lab[i0 + t];
        sqJ[t] = g_sq[j0 + t];  lbJ[t] = g_lab[j0 + t];
    }

    // fill tiles (convert to tf32 bits in-place)
    const float4* F4 = (const float4*)F;
    for (int v = t; v < TILE * 32; v += 256) {
        int r  = v >> 5;
        int c4 = v & 31;
        float4 fa = F4[(size_t)(i0 + r) * 32 + c4];
        uint4 ta = { f2tf32(fa.x), f2tf32(fa.y), f2tf32(fa.z), f2tf32(fa.w) };
        *(uint4*)(As + r * SSTR + c4 * 4) = ta;
        if (!diag) {
            float4 fb = F4[(size_t)(j0 + r) * 32 + c4];
            uint4 tb = { f2tf32(fb.x), f2tf32(fb.y), f2tf32(fb.z), f2tf32(fb.w) };
            *(uint4*)(Bs + r * SSTR + c4 * 4) = tb;
        }
    }
    __syncthreads();

    const float* Bp = diag ? As : Bs;

    int wm = wid & 1;          // 0..1  -> row block of 64
    int wn = wid >> 1;         // 0..3  -> col block of 32
    int mbase = wm * 64;
    int nbase = wn * 32;

    float acc[4][4][4];
    #pragma unroll
    for (int mf = 0; mf < 4; mf++)
        #pragma unroll
        for (int nf = 0; nf < 4; nf++)
            #pragma unroll
            for (int rr = 0; rr < 4; rr++) acc[mf][nf][rr] = 0.0f;

    #pragma unroll
    for (int k8 = 0; k8 < 16; k8++) {
        int kb = k8 * 8;
        uint32_t a[4][4];
        #pragma unroll
        for (int mf = 0; mf < 4; mf++) {
            const uint32_t* r0 = (const uint32_t*)(As + (mbase + 16 * mf + gid) * SSTR + kb);
            const uint32_t* r1 = (const uint32_t*)(As + (mbase + 16 * mf + gid + 8) * SSTR + kb);
            a[mf][0] = r0[tig];
            a[mf][1] = r1[tig];
            a[mf][2] = r0[tig + 4];
            a[mf][3] = r1[tig + 4];
        }
        uint32_t b[4][2];
        #pragma unroll
        for (int nf = 0; nf < 4; nf++) {
            const uint32_t* rn = (const uint32_t*)(Bp + (nbase + 8 * nf + gid) * SSTR + kb);
            b[nf][0] = rn[tig];
            b[nf][1] = rn[tig + 4];
        }
        #pragma unroll
        for (int mf = 0; mf < 4; mf++)
            #pragma unroll
            for (int nf = 0; nf < 4; nf++)
                mma_tf32(acc[mf][nf], a[mf][0], a[mf][1], a[mf][2], a[mf][3],
                         b[nf][0], b[nf][1]);
    }

    // ---- fused loss epilogue on register fragments ----
    float lsum = 0.0f;
    int   lcnt = 0;
    #pragma unroll
    for (int mf = 0; mf < 4; mf++) {
        #pragma unroll
        for (int rr = 0; rr < 2; rr++) {          // row halves (+0 / +8)
            int m = mbase + 16 * mf + gid + 8 * rr;
            float sqi = sqI[m];
            int   li  = lbI[m];
            #pragma unroll
            for (int nf = 0; nf < 4; nf++) {
                #pragma unroll
                for (int cc = 0; cc < 2; cc++) {  // col pair
                    int n = nbase + 8 * nf + tig * 2 + cc;
                    float dot = acc[mf][nf][rr * 2 + cc];
                    if (diag && m == n) continue;
                    float d2 = fmaxf(sqi + sqJ[n] - 2.0f * dot, 0.0f);
                    if (li == lbJ[n]) {
                        lsum += d2;
                        lcnt++;
                    } else if (d2 < MARGIN * MARGIN) {  // ~never taken
                        float h = MARGIN - sqrtf(d2);
                        lsum += h * h;
                    }
                }
            }
        }
    }

    // deterministic block reduction
    #pragma unroll
    for (int off = 16; off; off >>= 1) {
        lsum += __shfl_xor_sync(0xffffffffu, lsum, off);
        lcnt += __shfl_xor_sync(0xffffffffu, lcnt, off);
    }
    __shared__ float rbuf[8];
    __shared__ int   rcnt[8];
    if (lane == 0) { rbuf[wid] = lsum; rcnt[wid] = lcnt; }
    __syncthreads();
    if (t == 0) {
        float s = 0.0f; long long c = 0;
        #pragma unroll
        for (int wd = 0; wd < 8; wd++) { s += rbuf[wd]; c += rcnt[wd]; }
        float fac = diag ? 1.0f : 2.0f;
        g_partials[blockIdx.x] = s * fac;
        g_poscnt[blockIdx.x]   = c * (diag ? 1LL : 2LL);
    }
}

// ---------------------------------------------------------------------------
// Kernel 2: fixed-order finalize reduction -> scalar loss.
// ---------------------------------------------------------------------------
__global__ void finalize_kernel(float* __restrict__ out) {
    int t = threadIdx.x;
    double s = 0.0; long long c = 0;
    for (int i = t; i < NBLK; i += 256) {
        s += (double)g_partials[i];
        c += g_poscnt[i];
    }
    __shared__ double    sd[256];
    __shared__ long long sc[256];
    sd[t] = s; sc[t] = c;
    __syncthreads();
    for (int off = 128; off; off >>= 1) {
        if (t < off) { sd[t] += sd[t + off]; sc[t] += sc[t + off]; }
        __syncthreads();
    }
    if (t == 0) {
        double total = sd[0];
        double denom = (double)((long long)BN * (BN - 1));
        out[0] = (float)(sc[0] > 0 ? total / denom : total);
    }
}

// ---------------------------------------------------------------------------
extern "C" void kernel_launch(void* const* d_in, const int* in_sizes, int n_in,
                              void* d_out, int out_size) {
    const float* F      = (const float*)d_in[0];
    const void*  labels = d_in[1];
    float*       out    = (float*)d_out;

    size_t smem_bytes = (size_t)2 * TILE * SSTR * sizeof(float)   // A+B tiles
                      + 2 * TILE * sizeof(float)                  // sqI/sqJ
                      + 2 * TILE * sizeof(int);                   // lbI/lbJ
    cudaFuncSetAttribute(tile_kernel,
                         cudaFuncAttributeMaxDynamicSharedMemorySize,
                         (int)smem_bytes);

    prep_kernel<<<BN / 8, 256>>>(F, labels);
    tile_kernel<<<NBLK, 256, smem_bytes>>>(F);
    finalize_kernel<<<1, 256>>>(out);
}

// round 7
// speedup vs baseline: 2.4882x; 1.3591x over previous
#include <cuda_runtime.h>
#include <cstdint>

// FeaturesLoss: mma.sync m16n8k8 tf32, 128x256 CTA tiles (64x64 per warp),
// cp.async 4-chunk K pipeline, ordered-pair (j>i, x2) triangular coverage.

#define BN    8192
#define DIM   128
#define TM    128                   // CTA tile rows (i)
#define TNJ   256                   // CTA tile cols (j)
#define NT    (BN / TM)             // 64 row tiles
#define NBLK2 1056                  // sum_{bi} (32 - bi/2)
#define MARGIN 2.0f

#define CH     32                   // K per chunk
#define NCHUNK 4
#define RPITCH 144                  // bytes per row in a chunk (36 floats)
#define ACHUNK (TM  * RPITCH)       // 18432
#define BCHUNK (TNJ * RPITCH)       // 36864
#define SM_A   0
#define SM_B   (NCHUNK * ACHUNK)                    // 73728
#define SM_STG (SM_B + NCHUNK * BCHUNK)             // 221184
#define SM_SQI (SM_STG)
#define SM_SQJ (SM_SQI + TM * 4)
#define SM_LBI (SM_SQJ + TNJ * 4)
#define SM_LBJ (SM_LBI + TM * 4)
#define SM_TOT (SM_LBJ + TNJ * 4)                   // 224256

__device__ float      g_sq[BN];
__device__ int        g_lab[BN];
__device__ float      g_partials[NBLK2];
__device__ long long  g_poscnt[NBLK2];

__device__ __forceinline__ uint32_t smem_u32(const void* p) {
    uint32_t a;
    asm("{ .reg .u64 t; cvta.to.shared.u64 t, %1; cvt.u32.u64 %0, t; }" : "=r"(a) : "l"(p));
    return a;
}
__device__ __forceinline__ void cp16(uint32_t dst, const void* src) {
    asm volatile("cp.async.cg.shared.global [%0], [%1], 16;" :: "r"(dst), "l"(src));
}
__device__ __forceinline__ void cp_commit() {
    asm volatile("cp.async.commit_group;" ::: "memory");
}
template<int N> __device__ __forceinline__ void cp_wait() {
    asm volatile("cp.async.wait_group %0;" :: "n"(N) : "memory");
}
__device__ __forceinline__ void mma_tf32(float c[4], uint32_t a0, uint32_t a1,
                                         uint32_t a2, uint32_t a3,
                                         uint32_t b0, uint32_t b1) {
    asm volatile(
        "mma.sync.aligned.m16n8k8.row.col.f32.tf32.tf32.f32 "
        "{%0,%1,%2,%3}, {%4,%5,%6,%7}, {%8,%9}, {%0,%1,%2,%3};"
        : "+f"(c[0]), "+f"(c[1]), "+f"(c[2]), "+f"(c[3])
        : "r"(a0), "r"(a1), "r"(a2), "r"(a3), "r"(b0), "r"(b1));
}

// ---------------------------------------------------------------------------
__global__ void prep_kernel(const float* __restrict__ F,
                            const void* __restrict__ labels_raw) {
    int warp = (blockIdx.x * blockDim.x + threadIdx.x) >> 5;
    int lane = threadIdx.x & 31;
    if (warp >= BN) return;

    const int* w = (const int*)labels_raw;
    int probe = w[2 * lane + 1];
    unsigned is64 = __all_sync(0xffffffffu, probe == 0);

    const float4* row = (const float4*)(F + (size_t)warp * DIM);
    float4 f = row[lane];
    float s = f.x * f.x + f.y * f.y + f.z * f.z + f.w * f.w;
    #pragma unroll
    for (int off = 16; off; off >>= 1)
        s += __shfl_xor_sync(0xffffffffu, s, off);

    if (lane == 0) {
        g_sq[warp] = s;
        int lab;
        if (is64) lab = (int)((const long long*)labels_raw)[warp];
        else      lab = w[warp];
        g_lab[warp] = lab;
    }
}

// ---------------------------------------------------------------------------
// One 128x256 pair tile per CTA; pairs counted iff gj > gi (weight x2).
// ---------------------------------------------------------------------------
__global__ void __launch_bounds__(256, 1)
tile_kernel(const float* __restrict__ F) {
    extern __shared__ char smem[];
    uint32_t sbase = smem_u32(smem);

    int t = threadIdx.x;
    int wid = t >> 5, lane = t & 31;
    int gid = lane >> 2, tig = lane & 3;

    // block id -> (bi, bjp): col-pair bjp covers j-tiles {2bjp, 2bjp+1}; bjp >= bi/2
    int idx = blockIdx.x;
    int bi = 0;
    while (idx >= 32 - (bi >> 1)) { idx -= 32 - (bi >> 1); bi++; }
    int bjp = (bi >> 1) + idx;
    int i0 = bi * TM, j0 = bjp * TNJ;

    // issue cp.async chunks (4 commit groups: chunk c = K columns [32c, 32c+32))
    #pragma unroll
    for (int c = 0; c < NCHUNK; c++) {
        for (int s = t; s < TM * 8; s += 256) {       // A: 1024 segs of 16B
            int r = s >> 3, q = s & 7;
            cp16(sbase + SM_A + c * ACHUNK + r * RPITCH + q * 16,
                 F + (size_t)(i0 + r) * DIM + c * CH + q * 4);
        }
        for (int s = t; s < TNJ * 8; s += 256) {      // B: 2048 segs
            int r = s >> 3, q = s & 7;
            cp16(sbase + SM_B + c * BCHUNK + r * RPITCH + q * 16,
                 F + (size_t)(j0 + r) * DIM + c * CH + q * 4);
        }
        cp_commit();
    }

    // stage sq/labels while copies fly
    float* sqI = (float*)(smem + SM_SQI);
    float* sqJ = (float*)(smem + SM_SQJ);
    int*   lbI = (int*)  (smem + SM_LBI);
    int*   lbJ = (int*)  (smem + SM_LBJ);
    if (t < TM) { sqI[t] = g_sq[i0 + t]; lbI[t] = g_lab[i0 + t]; }
    { int j = t; sqJ[j] = g_sq[j0 + j]; lbJ[j] = g_lab[j0 + j];
      j = t + 256; if (j < TNJ) { } }               // TNJ==256: one element each
    // (t covers 0..255 == TNJ exactly; TM handled above)

    int wm = wid & 1;            // row block of 64
    int wn = wid >> 1;           // col block of 64
    int mbase = wm * 64;
    int nbase = wn * 64;

    float acc[4][8][4];
    #pragma unroll
    for (int mf = 0; mf < 4; mf++)
        #pragma unroll
        for (int nf = 0; nf < 8; nf++)
            #pragma unroll
            for (int rr = 0; rr < 4; rr++) acc[mf][nf][rr] = 0.0f;

    // K loop: 4 chunks x 4 k8-steps
    #pragma unroll
    for (int c = 0; c < NCHUNK; c++) {
        if (c == 0) cp_wait<3>();
        else if (c == 1) cp_wait<2>();
        else if (c == 2) cp_wait<1>();
        else cp_wait<0>();
        __syncthreads();

        const float* Ac = (const float*)(smem + SM_A + c * ACHUNK);
        const float* Bc = (const float*)(smem + SM_B + c * BCHUNK);

        #pragma unroll
        for (int k8 = 0; k8 < 4; k8++) {
            int kb = k8 * 8;
            uint32_t a[4][4];
            #pragma unroll
            for (int mf = 0; mf < 4; mf++) {
                const uint32_t* r0 = (const uint32_t*)(Ac + (size_t)(mbase + 16 * mf + gid) * 36 + kb);
                const uint32_t* r1 = (const uint32_t*)(Ac + (size_t)(mbase + 16 * mf + gid + 8) * 36 + kb);
                a[mf][0] = r0[tig];
                a[mf][1] = r1[tig];
                a[mf][2] = r0[tig + 4];
                a[mf][3] = r1[tig + 4];
            }
            uint32_t b[8][2];
            #pragma unroll
            for (int nf = 0; nf < 8; nf++) {
                const uint32_t* rn = (const uint32_t*)(Bc + (size_t)(nbase + 8 * nf + gid) * 36 + kb);
                b[nf][0] = rn[tig];
                b[nf][1] = rn[tig + 4];
            }
            #pragma unroll
            for (int mf = 0; mf < 4; mf++)
                #pragma unroll
                for (int nf = 0; nf < 8; nf++)
                    mma_tf32(acc[mf][nf], a[mf][0], a[mf][1], a[mf][2], a[mf][3],
                             b[nf][0], b[nf][1]);
        }
    }

    // ---- fused epilogue: count ordered pairs gj > gi, weight x2 ----
    float lsum = 0.0f;
    int   lcnt = 0;
    #pragma unroll
    for (int mf = 0; mf < 4; mf++) {
        #pragma unroll
        for (int rr = 0; rr < 2; rr++) {
            int m  = mbase + 16 * mf + gid + 8 * rr;
            int gi = i0 + m;
            float sqi = sqI[m];
            int   li  = lbI[m];
            #pragma unroll
            for (int nf = 0; nf < 8; nf++) {
                #pragma unroll
                for (int cc = 0; cc < 2; cc++) {
                    int n  = nbase + 8 * nf + tig * 2 + cc;
                    int gj = j0 + n;
                    if (gj <= gi) continue;
                    float dot = acc[mf][nf][rr * 2 + cc];
                    float d2 = fmaxf(sqi + sqJ[n] - 2.0f * dot, 0.0f);
                    if (li == lbJ[n]) {
                        lsum += d2;
                        lcnt++;
                    } else if (d2 < MARGIN * MARGIN) {   // ~never taken
                        float h = MARGIN - sqrtf(d2);
                        lsum += h * h;
                    }
                }
            }
        }
    }

    // deterministic block reduction
    #pragma unroll
    for (int off = 16; off; off >>= 1) {
        lsum += __shfl_xor_sync(0xffffffffu, lsum, off);
        lcnt += __shfl_xor_sync(0xffffffffu, lcnt, off);
    }
    __shared__ float rbuf[8];
    __shared__ int   rcnt[8];
    if (lane == 0) { rbuf[wid] = lsum; rcnt[wid] = lcnt; }
    __syncthreads();
    if (t == 0) {
        float s = 0.0f; long long c = 0;
        #pragma unroll
        for (int wd = 0; wd < 8; wd++) { s += rbuf[wd]; c += rcnt[wd]; }
        g_partials[blockIdx.x] = s * 2.0f;     // ordered pairs -> x2
        g_poscnt[blockIdx.x]   = c * 2LL;
    }
}

// ---------------------------------------------------------------------------
__global__ void finalize_kernel(float* __restrict__ out) {
    int t = threadIdx.x;
    double s = 0.0; long long c = 0;
    for (int i = t; i < NBLK2; i += 256) {
        s += (double)g_partials[i];
        c += g_poscnt[i];
    }
    __shared__ double    sd[256];
    __shared__ long long sc[256];
    sd[t] = s; sc[t] = c;
    __syncthreads();
    for (int off = 128; off; off >>= 1) {
        if (t < off) { sd[t] += sd[t + off]; sc[t] += sc[t + off]; }
        __syncthreads();
    }
    if (t == 0) {
        double total = sd[0];
        double denom = (double)((long long)BN * (BN - 1));
        out[0] = (float)(sc[0] > 0 ? total / denom : total);
    }
}

// ---------------------------------------------------------------------------
extern "C" void kernel_launch(void* const* d_in, const int* in_sizes, int n_in,
                              void* d_out, int out_size) {
    const float* F      = (const float*)d_in[0];
    const void*  labels = d_in[1];
    float*       out    = (float*)d_out;

    cudaFuncSetAttribute(tile_kernel,
                         cudaFuncAttributeMaxDynamicSharedMemorySize, SM_TOT);

    prep_kernel<<<BN / 8, 256>>>(F, labels);
    tile_kernel<<<NBLK2, 256, SM_TOT>>>(F);
    finalize_kernel<<<1, 256>>>(out);
}